// round 3
// baseline (speedup 1.0000x reference)
#include <cuda_runtime.h>

typedef unsigned long long ull_t;

#define D      64
#define H      128
#define GDIM   64
#define NMAX   100000
#define WARPS  8
#define EPW    8

// ---------- packed fp32x2 helpers ----------
static __device__ __forceinline__ ull_t ffma2(ull_t a, ull_t b, ull_t c) {
    ull_t d;
    asm("fma.rn.f32x2 %0, %1, %2, %3;" : "=l"(d) : "l"(a), "l"(b), "l"(c));
    return d;
}
static __device__ __forceinline__ ull_t fadd2(ull_t a, ull_t b) {
    ull_t d;
    asm("add.rn.f32x2 %0, %1, %2;" : "=l"(d) : "l"(a), "l"(b));
    return d;
}
static __device__ __forceinline__ ull_t pack2(float lo, float hi) {
    ull_t r;
    asm("mov.b64 %0, {%1, %2};" : "=l"(r) : "f"(lo), "f"(hi));
    return r;
}
static __device__ __forceinline__ void unpack2(ull_t v, float& lo, float& hi) {
    asm("mov.b64 {%0, %1}, %2;" : "=f"(lo), "=f"(hi) : "l"(v));
}

// ---------- device scratch ----------
__device__ float g_P[(size_t)NMAX * H];   // x @ W1[64:128]
__device__ float g_Q[(size_t)NMAX * H];   // x @ W1[128:192] + R[batch[n]]
__device__ float g_R[GDIM * H];           // u @ W1[192:256] + b1

// ================= R = u @ W1_glob + b1 =================
__global__ void k_preR(const float* __restrict__ u,
                       const float* __restrict__ W1,
                       const float* __restrict__ b1) {
    __shared__ float us[D];
    int g = blockIdx.x;
    int j = threadIdx.x;
    if (j < D) us[j] = u[g * D + j];
    __syncthreads();
    float acc = b1[j];
#pragma unroll 8
    for (int k = 0; k < D; k++)
        acc += us[k] * W1[(192 + k) * H + j];
    g_R[g * H + j] = acc;
}

// ================= P, Q' node projections =================
__global__ void k_prePQ(const float* __restrict__ x,
                        const float* __restrict__ W1,
                        const int* __restrict__ batch,
                        int N) {
    __shared__ __align__(16) float xs[8][D];
    int t = threadIdx.x;
    int base = blockIdx.x * 8;

    {
        int nn = base + (t >> 4);
        int part = t & 15;
        if (nn >= N) nn = N - 1;
        ((float4*)&xs[0][0])[t] = ((const float4*)x)[(size_t)nn * 16 + part];
    }
    __syncthreads();

    int  jp  = t & 63;
    bool isQ = (t >= 64);
    const float* W = W1 + (isQ ? 128 : 64) * H + 2 * jp;

    ull_t acc[8];
#pragma unroll
    for (int m = 0; m < 8; m++) acc[m] = pack2(0.0f, 0.0f);

#pragma unroll 4
    for (int k = 0; k < D; k += 2) {
        ull_t w0 = *(const ull_t*)(W + (size_t)k * H);
        ull_t w1 = *(const ull_t*)(W + (size_t)(k + 1) * H);
#pragma unroll
        for (int m = 0; m < 8; m++) {
            ull_t xv = *(const ull_t*)&xs[m][k];
            float x0, x1;
            unpack2(xv, x0, x1);
            acc[m] = ffma2(pack2(x0, x0), w0, acc[m]);
            acc[m] = ffma2(pack2(x1, x1), w1, acc[m]);
        }
    }

    float* dst = isQ ? g_Q : g_P;
#pragma unroll
    for (int m = 0; m < 8; m++) {
        int n = base + m;
        if (n >= N) break;
        ull_t v = acc[m];
        if (isQ) {
            int bg = batch[n];
            v = fadd2(v, *(const ull_t*)(g_R + bg * H + 2 * jp));
        }
        *(ull_t*)(dst + (size_t)n * H + 2 * jp) = v;
    }
}

// ================= edge kernel =================
// Lane l owns output columns j = 4l .. 4l+3: acc0=(4l,4l+1), acc1=(4l+2,4l+3).
// Weights in natural row-major smem -> one LDS.128 per k-row per lane.
// e / h1 staged duplicated ((v,v) pairs) -> broadcast ulonglong2 loads feed
// FFMA2 directly with no repack MOVs.
__global__ __launch_bounds__(256, 1) void k_edge(
    const float* __restrict__ e,
    const float* __restrict__ W1,
    const float* __restrict__ W2,
    const float* __restrict__ b2,
    const float* __restrict__ ln_g,
    const float* __restrict__ ln_b,
    const int* __restrict__ eidx,
    float* __restrict__ out,
    int E) {
    extern __shared__ float smem[];
    float* As  = smem;                 // 64*128 f   (W1 rows 0..63)
    float* W2s = As + D * H;           // 128*128 f
    float* stg = W2s + H * H;          // WARPS*EPW*256 f

    int tid = threadIdx.x;
#pragma unroll 4
    for (int i = tid; i < D * H / 4; i += 256)
        ((float4*)As)[i] = ((const float4*)W1)[i];
#pragma unroll 4
    for (int i = tid; i < H * H / 4; i += 256)
        ((float4*)W2s)[i] = ((const float4*)W2)[i];
    __syncthreads();

    int warp = tid >> 5, lane = tid & 31;
    float* wsd = stg + warp * (EPW * 256);

    ulonglong2 b2p = *(const ulonglong2*)(b2 + 4 * lane);
    float4 lg = *(const float4*)(ln_g + 4 * lane);
    float4 lb = *(const float4*)(ln_b + 4 * lane);

    int ngroups = (E + EPW - 1) / EPW;

    for (int grp = blockIdx.x * WARPS + warp; grp < ngroups;
         grp += gridDim.x * WARPS) {
        int i0 = grp * EPW;
        __syncwarp();

        int rowm = 0, colm = 0;
        if (lane < EPW) {
            int ee = i0 + lane;
            int ec = ee < E ? ee : E - 1;
            rowm = eidx[ec];
            colm = eidx[(size_t)E + ec];
        }

        ull_t acc0[EPW], acc1[EPW];
#pragma unroll
        for (int m = 0; m < EPW; m++) {
            int r = __shfl_sync(0xffffffffu, rowm, m);
            int c = __shfl_sync(0xffffffffu, colm, m);
            int im = i0 + m;
            int ic = im < E ? im : E - 1;
            // stage e row duplicated: e[2l],e[2l] | e[2l+1],e[2l+1]
            float2 v = ((const float2*)e)[(size_t)ic * 32 + lane];
            *(float4*)(wsd + m * 256 + 4 * lane) =
                make_float4(v.x, v.x, v.y, v.y);
            // gather P[col] + Q'[row] for this lane's 4 columns
            ulonglong2 p = *(const ulonglong2*)(g_P + (size_t)c * H + 4 * lane);
            ulonglong2 q = *(const ulonglong2*)(g_Q + (size_t)r * H + 4 * lane);
            acc0[m] = fadd2(p.x, q.x);
            acc1[m] = fadd2(p.y, q.y);
        }
        __syncwarp();

        // ---------------- GEMM1: acc += e @ A   (K = 64) ----------------
#pragma unroll 4
        for (int k = 0; k < D; k += 2) {
            ulonglong2 w0 = *(const ulonglong2*)(As + (k + 0) * H + 4 * lane);
            ulonglong2 w1 = *(const ulonglong2*)(As + (k + 1) * H + 4 * lane);
#pragma unroll
            for (int m = 0; m < EPW; m++) {
                ulonglong2 ev = *(const ulonglong2*)(wsd + m * 256 + 2 * k);
                acc0[m] = ffma2(ev.x, w0.x, acc0[m]);
                acc1[m] = ffma2(ev.x, w0.y, acc1[m]);
                acc0[m] = ffma2(ev.y, w1.x, acc0[m]);
                acc1[m] = ffma2(ev.y, w1.y, acc1[m]);
            }
        }
        __syncwarp();

        // relu + restage h1 duplicated (value h1[j], j = 4l..4l+3, at float
        // offset 2j)
#pragma unroll
        for (int m = 0; m < EPW; m++) {
            float a0, a1, a2, a3;
            unpack2(acc0[m], a0, a1);
            unpack2(acc1[m], a2, a3);
            a0 = fmaxf(a0, 0.0f); a1 = fmaxf(a1, 0.0f);
            a2 = fmaxf(a2, 0.0f); a3 = fmaxf(a3, 0.0f);
            *(float4*)(wsd + m * 256 + 8 * lane) =
                make_float4(a0, a0, a1, a1);
            *(float4*)(wsd + m * 256 + 8 * lane + 4) =
                make_float4(a2, a2, a3, a3);
        }
        __syncwarp();

#pragma unroll
        for (int m = 0; m < EPW; m++) { acc0[m] = b2p.x; acc1[m] = b2p.y; }

        // ---------------- GEMM2: acc += h1 @ W2  (K = 128) ----------------
#pragma unroll 4
        for (int k = 0; k < H; k += 2) {
            ulonglong2 w0 = *(const ulonglong2*)(W2s + (k + 0) * H + 4 * lane);
            ulonglong2 w1 = *(const ulonglong2*)(W2s + (k + 1) * H + 4 * lane);
#pragma unroll
            for (int m = 0; m < EPW; m++) {
                ulonglong2 ev = *(const ulonglong2*)(wsd + m * 256 + 2 * k);
                acc0[m] = ffma2(ev.x, w0.x, acc0[m]);
                acc1[m] = ffma2(ev.x, w0.y, acc1[m]);
                acc0[m] = ffma2(ev.y, w1.x, acc0[m]);
                acc1[m] = ffma2(ev.y, w1.y, acc1[m]);
            }
        }

        // ---------------- relu + LayerNorm + store ----------------
#pragma unroll
        for (int m = 0; m < EPW; m++) {
            int im = i0 + m;
            float a0, a1, a2, a3;
            unpack2(acc0[m], a0, a1);
            unpack2(acc1[m], a2, a3);
            a0 = fmaxf(a0, 0.0f); a1 = fmaxf(a1, 0.0f);
            a2 = fmaxf(a2, 0.0f); a3 = fmaxf(a3, 0.0f);
            float s  = a0 + a1 + a2 + a3;
            float sq = a0 * a0 + a1 * a1 + a2 * a2 + a3 * a3;
#pragma unroll
            for (int off = 16; off; off >>= 1) {
                s  += __shfl_xor_sync(0xffffffffu, s,  off);
                sq += __shfl_xor_sync(0xffffffffu, sq, off);
            }
            float mean = s * (1.0f / H);
            float var  = sq * (1.0f / H) - mean * mean;
            float rstd = rsqrtf(var + 1e-5f);
            float y0 = (a0 - mean) * rstd * lg.x + lb.x;
            float y1 = (a1 - mean) * rstd * lg.y + lb.y;
            float y2 = (a2 - mean) * rstd * lg.z + lb.z;
            float y3 = (a3 - mean) * rstd * lg.w + lb.w;
            if (im < E) {
                *(float4*)(out + (size_t)im * H + 4 * lane) =
                    make_float4(y0, y1, y2, y3);
            }
        }
    }
}

// ================= launch =================
extern "C" void kernel_launch(void* const* d_in, const int* in_sizes, int n_in,
                              void* d_out, int out_size) {
    const float* x     = (const float*)d_in[0];
    const float* e     = (const float*)d_in[1];
    const float* u     = (const float*)d_in[2];
    const float* W1    = (const float*)d_in[3];
    const float* b1    = (const float*)d_in[4];
    const float* W2    = (const float*)d_in[5];
    const float* b2    = (const float*)d_in[6];
    const float* ln_g  = (const float*)d_in[7];
    const float* ln_b  = (const float*)d_in[8];
    const int*   eidx  = (const int*)d_in[9];
    const int*   batch = (const int*)d_in[10];
    float*       out   = (float*)d_out;

    int N = in_sizes[0] / D;   // 100000
    int E = in_sizes[1] / D;   // 1000000

    const int SMEM_EDGE = (D * H + H * H + WARPS * EPW * 256) * (int)sizeof(float); // 160 KB
    cudaFuncSetAttribute(k_edge, cudaFuncAttributeMaxDynamicSharedMemorySize, SMEM_EDGE);

    k_preR<<<GDIM, H>>>(u, W1, b1);
    k_prePQ<<<(N + 7) / 8, 128>>>(x, W1, batch, N);
    k_edge<<<152, 256, SMEM_EDGE>>>(e, W1, W2, b2, ln_g, ln_b, eidx, out, E);
}

// round 4
// speedup vs baseline: 1.8860x; 1.8860x over previous
#include <cuda_runtime.h>
#include <cuda_bf16.h>

typedef unsigned long long ull_t;
typedef unsigned int uint32;

#define D      64
#define H      128
#define GDIM   64
#define NMAX   100000

// ---------- packed fp32x2 helpers (pre-kernels) ----------
static __device__ __forceinline__ ull_t ffma2(ull_t a, ull_t b, ull_t c) {
    ull_t d;
    asm("fma.rn.f32x2 %0, %1, %2, %3;" : "=l"(d) : "l"(a), "l"(b), "l"(c));
    return d;
}
static __device__ __forceinline__ ull_t fadd2(ull_t a, ull_t b) {
    ull_t d;
    asm("add.rn.f32x2 %0, %1, %2;" : "=l"(d) : "l"(a), "l"(b));
    return d;
}
static __device__ __forceinline__ ull_t pack2(float lo, float hi) {
    ull_t r;
    asm("mov.b64 %0, {%1, %2};" : "=l"(r) : "f"(lo), "f"(hi));
    return r;
}
static __device__ __forceinline__ void unpack2(ull_t v, float& lo, float& hi) {
    asm("mov.b64 {%0, %1}, %2;" : "=f"(lo), "=f"(hi) : "l"(v));
}

// ---------- device scratch ----------
__device__ float g_P[(size_t)NMAX * H];   // x @ W1[64:128]
__device__ float g_Q[(size_t)NMAX * H];   // x @ W1[128:192] + R[batch[n]]  (b1 folded)
__device__ float g_R[GDIM * H];           // u @ W1[192:256] + b1

// ---------- bf16 split/pack helpers ----------
// pack(x,y): x -> low 16 bits, y -> high 16 bits
static __device__ __forceinline__ uint32 bpack(__nv_bfloat16 x, __nv_bfloat16 y) {
    __nv_bfloat162 t = __halves2bfloat162(x, y);
    return *reinterpret_cast<uint32*>(&t);
}
static __device__ __forceinline__ void splitpack(float x, float y,
                                                 uint32& hi, uint32& lo) {
    __nv_bfloat16 xh = __float2bfloat16_rn(x);
    __nv_bfloat16 yh = __float2bfloat16_rn(y);
    hi = bpack(xh, yh);
    __nv_bfloat16 xl = __float2bfloat16_rn(x - __bfloat162float(xh));
    __nv_bfloat16 yl = __float2bfloat16_rn(y - __bfloat162float(yh));
    lo = bpack(xl, yl);
}

// mma.sync m16n8k16 bf16, fp32 acc
static __device__ __forceinline__ void mma4(float* d, const uint32* a,
                                            uint32 b0, uint32 b1) {
    asm("mma.sync.aligned.m16n8k16.row.col.f32.bf16.bf16.f32 "
        "{%0,%1,%2,%3}, {%4,%5,%6,%7}, {%8,%9}, {%0,%1,%2,%3};"
        : "+f"(d[0]), "+f"(d[1]), "+f"(d[2]), "+f"(d[3])
        : "r"(a[0]), "r"(a[1]), "r"(a[2]), "r"(a[3]), "r"(b0), "r"(b1));
}

// ================= R = u @ W1_glob + b1 =================
__global__ void k_preR(const float* __restrict__ u,
                       const float* __restrict__ W1,
                       const float* __restrict__ b1) {
    __shared__ float us[D];
    int g = blockIdx.x;
    int j = threadIdx.x;
    if (j < D) us[j] = u[g * D + j];
    __syncthreads();
    float acc = b1[j];
#pragma unroll 8
    for (int k = 0; k < D; k++)
        acc += us[k] * W1[(192 + k) * H + j];
    g_R[g * H + j] = acc;
}

// ================= P, Q' node projections =================
__global__ void k_prePQ(const float* __restrict__ x,
                        const float* __restrict__ W1,
                        const int* __restrict__ batch,
                        int N) {
    __shared__ __align__(16) float xs[8][D];
    int t = threadIdx.x;
    int base = blockIdx.x * 8;
    {
        int nn = base + (t >> 4);
        int part = t & 15;
        if (nn >= N) nn = N - 1;
        ((float4*)&xs[0][0])[t] = ((const float4*)x)[(size_t)nn * 16 + part];
    }
    __syncthreads();

    int  jp  = t & 63;
    bool isQ = (t >= 64);
    const float* W = W1 + (isQ ? 128 : 64) * H + 2 * jp;

    ull_t acc[8];
#pragma unroll
    for (int m = 0; m < 8; m++) acc[m] = pack2(0.0f, 0.0f);

#pragma unroll 4
    for (int k = 0; k < D; k += 2) {
        ull_t w0 = *(const ull_t*)(W + (size_t)k * H);
        ull_t w1 = *(const ull_t*)(W + (size_t)(k + 1) * H);
#pragma unroll
        for (int m = 0; m < 8; m++) {
            ull_t xv = *(const ull_t*)&xs[m][k];
            float x0, x1;
            unpack2(xv, x0, x1);
            acc[m] = ffma2(pack2(x0, x0), w0, acc[m]);
            acc[m] = ffma2(pack2(x1, x1), w1, acc[m]);
        }
    }

    float* dst = isQ ? g_Q : g_P;
#pragma unroll
    for (int m = 0; m < 8; m++) {
        int n = base + m;
        if (n >= N) break;
        ull_t v = acc[m];
        if (isQ) {
            int bg = batch[n];
            v = fadd2(v, *(const ull_t*)(g_R + bg * H + 2 * jp));
        }
        *(ull_t*)(dst + (size_t)n * H + 2 * jp) = v;
    }
}

// ================= edge kernel (tensor-core path) =================
// Per warp per group: 16 edges (M=16). GEMM1: h1 = e@W1[0:64] + (P[col]+Q[row]),
// relu; GEMM2: out = LN(relu(h1@W2 + b2)). bf16 hi/lo split, 3-term mma.
// GEMM1 D-fragments convert in-register to GEMM2 A-fragments (same ownership).
#define PQ_STRIDE 132   // 16 rows of 128 fp32, padded to kill bank conflicts

__global__ __launch_bounds__(256, 1) void k_edge_mma(
    const float* __restrict__ e,
    const float* __restrict__ W1,
    const float* __restrict__ W2,
    const float* __restrict__ b2,
    const float* __restrict__ ln_g,
    const float* __restrict__ ln_b,
    const int* __restrict__ eidx,
    float* __restrict__ out,
    int E) {
    extern __shared__ __align__(16) char smem_raw[];
    uint4* sB1 = (uint4*)smem_raw;                    // [4][16][32]  (W1 frags hi+lo)
    uint4* sB2 = sB1 + 4 * 16 * 32;                   // [8][16][32]  (W2 frags hi+lo)
    float* sb2 = (float*)(sB2 + 8 * 16 * 32);         // [128]
    float* slg = sb2 + 128;                           // [128]
    float* slb = slg + 128;                           // [128]
    float* spq = slb + 128;                           // [8][16*PQ_STRIDE]

    int tid = threadIdx.x;

    // ---- prepack B fragments (lane layout: n = 8nf + lane/4, k = 16kf + (lane%4)*2) ----
    for (int idx = tid; idx < 4 * 16 * 32; idx += 256) {
        int lane = idx & 31, nf = (idx >> 5) & 15, kf = idx >> 9;
        int n  = nf * 8 + (lane >> 2);
        int k0 = kf * 16 + (lane & 3) * 2;
        float w00 = W1[(size_t)(k0    ) * H + n];
        float w01 = W1[(size_t)(k0 + 1) * H + n];
        float w10 = W1[(size_t)(k0 + 8) * H + n];
        float w11 = W1[(size_t)(k0 + 9) * H + n];
        uint32 b0h, b0l, b1h, b1l;
        splitpack(w00, w01, b0h, b0l);
        splitpack(w10, w11, b1h, b1l);
        sB1[idx] = make_uint4(b0h, b1h, b0l, b1l);
    }
    for (int idx = tid; idx < 8 * 16 * 32; idx += 256) {
        int lane = idx & 31, nf = (idx >> 5) & 15, kf = idx >> 9;
        int n  = nf * 8 + (lane >> 2);
        int k0 = kf * 16 + (lane & 3) * 2;
        float w00 = W2[(size_t)(k0    ) * H + n];
        float w01 = W2[(size_t)(k0 + 1) * H + n];
        float w10 = W2[(size_t)(k0 + 8) * H + n];
        float w11 = W2[(size_t)(k0 + 9) * H + n];
        uint32 b0h, b0l, b1h, b1l;
        splitpack(w00, w01, b0h, b0l);
        splitpack(w10, w11, b1h, b1l);
        sB2[idx] = make_uint4(b0h, b1h, b0l, b1l);
    }
    for (int i = tid; i < 128; i += 256) {
        sb2[i] = b2[i]; slg[i] = ln_g[i]; slb[i] = ln_b[i];
    }
    __syncthreads();

    int lane = tid & 31;
    int warp = tid >> 5;
    float* pq = spq + warp * (16 * PQ_STRIDE);
    int g = lane >> 2;        // row group 0..7
    int c = lane & 3;         // col group 0..3

    int ngroups = (E + 15) >> 4;
    int gw = blockIdx.x * 8 + warp;
    int nwarps = gridDim.x * 8;

    for (int grp = gw; grp < ngroups; grp += nwarps) {
        int i0 = grp << 4;
        __syncwarp();

        // ---- stage P[col]+Q[row] (fp32 bias rows) into smem ----
        {
            int m = lane >> 1, h = lane & 1;
            int em = i0 + m; if (em >= E) em = E - 1;
            int r  = eidx[em];
            int cc = eidx[(size_t)E + em];
            const float4* Pr = (const float4*)(g_P + (size_t)cc * H + h * 64);
            const float4* Qr = (const float4*)(g_Q + (size_t)r  * H + h * 64);
            float4* dst = (float4*)(pq + m * PQ_STRIDE + h * 64);
#pragma unroll
            for (int i = 0; i < 16; i++) {
                float4 a = Pr[i], b = Qr[i];
                dst[i] = make_float4(a.x + b.x, a.y + b.y, a.z + b.z, a.w + b.w);
            }
        }

        // ---- load e-tile A fragments (rows g, g+8; 4 k-frags) ----
        uint32 aH[4][4], aL[4][4];
        {
            int e0i = i0 + g;     if (e0i >= E) e0i = E - 1;
            int e1i = i0 + g + 8; if (e1i >= E) e1i = E - 1;
            const float* er0 = e + (size_t)e0i * D;
            const float* er1 = e + (size_t)e1i * D;
#pragma unroll
            for (int kf = 0; kf < 4; kf++) {
                float2 v0 = *(const float2*)(er0 + kf * 16 + 2 * c);
                float2 v1 = *(const float2*)(er1 + kf * 16 + 2 * c);
                float2 v2 = *(const float2*)(er0 + kf * 16 + 2 * c + 8);
                float2 v3 = *(const float2*)(er1 + kf * 16 + 2 * c + 8);
                splitpack(v0.x, v0.y, aH[kf][0], aL[kf][0]);
                splitpack(v1.x, v1.y, aH[kf][1], aL[kf][1]);
                splitpack(v2.x, v2.y, aH[kf][2], aL[kf][2]);
                splitpack(v3.x, v3.y, aH[kf][3], aL[kf][3]);
            }
        }
        __syncwarp();

        // ---- acc init = pq (contains b1 + global term) ----
        float acc[16][4];
#pragma unroll
        for (int nf = 0; nf < 16; nf++) {
            float2 p0 = *(const float2*)(pq + g * PQ_STRIDE + nf * 8 + 2 * c);
            float2 p1 = *(const float2*)(pq + (g + 8) * PQ_STRIDE + nf * 8 + 2 * c);
            acc[nf][0] = p0.x; acc[nf][1] = p0.y;
            acc[nf][2] = p1.x; acc[nf][3] = p1.y;
        }

        // ---- GEMM1: acc += e @ W1[0:64]  (3-term bf16) ----
#pragma unroll
        for (int kf = 0; kf < 4; kf++) {
#pragma unroll
            for (int nf = 0; nf < 16; nf++) {
                uint4 B = sB1[(kf * 16 + nf) * 32 + lane];
                mma4(acc[nf], aH[kf], B.x, B.y);   // hi*hi
                mma4(acc[nf], aH[kf], B.z, B.w);   // hi*lo
                mma4(acc[nf], aL[kf], B.x, B.y);   // lo*hi
            }
        }

        // ---- relu + in-register D->A fragment conversion ----
        uint32 A2h[8][4], A2l[8][4];
#pragma unroll
        for (int kf = 0; kf < 8; kf++) {
            float* pa = acc[2 * kf];
            float* pb = acc[2 * kf + 1];
            float a0 = fmaxf(pa[0], 0.f), a1 = fmaxf(pa[1], 0.f);
            float a2 = fmaxf(pa[2], 0.f), a3 = fmaxf(pa[3], 0.f);
            float b0 = fmaxf(pb[0], 0.f), b1v = fmaxf(pb[1], 0.f);
            float b2v = fmaxf(pb[2], 0.f), b3 = fmaxf(pb[3], 0.f);
            splitpack(a0, a1, A2h[kf][0], A2l[kf][0]);
            splitpack(a2, a3, A2h[kf][1], A2l[kf][1]);
            splitpack(b0, b1v, A2h[kf][2], A2l[kf][2]);
            splitpack(b2v, b3, A2h[kf][3], A2l[kf][3]);
        }

        float acc2[16][4];
#pragma unroll
        for (int nf = 0; nf < 16; nf++) {
            acc2[nf][0] = 0.f; acc2[nf][1] = 0.f;
            acc2[nf][2] = 0.f; acc2[nf][3] = 0.f;
        }

        // ---- GEMM2: acc2 += relu(h1) @ W2 ----
#pragma unroll
        for (int kf = 0; kf < 8; kf++) {
#pragma unroll
            for (int nf = 0; nf < 16; nf++) {
                uint4 B = sB2[(kf * 16 + nf) * 32 + lane];
                mma4(acc2[nf], A2h[kf], B.x, B.y);
                mma4(acc2[nf], A2h[kf], B.z, B.w);
                mma4(acc2[nf], A2l[kf], B.x, B.y);
            }
        }

        // ---- + b2, relu, LayerNorm stats ----
        float s0 = 0.f, ss0 = 0.f, s8 = 0.f, ss8 = 0.f;
#pragma unroll
        for (int nf = 0; nf < 16; nf++) {
            float2 bb = *(const float2*)(sb2 + nf * 8 + 2 * c);
            float v0 = fmaxf(acc2[nf][0] + bb.x, 0.f);
            float v1 = fmaxf(acc2[nf][1] + bb.y, 0.f);
            float v2 = fmaxf(acc2[nf][2] + bb.x, 0.f);
            float v3 = fmaxf(acc2[nf][3] + bb.y, 0.f);
            acc2[nf][0] = v0; acc2[nf][1] = v1;
            acc2[nf][2] = v2; acc2[nf][3] = v3;
            s0 += v0 + v1;  ss0 += v0 * v0 + v1 * v1;
            s8 += v2 + v3;  ss8 += v2 * v2 + v3 * v3;
        }
        s0  += __shfl_xor_sync(0xffffffffu, s0, 1);
        s0  += __shfl_xor_sync(0xffffffffu, s0, 2);
        ss0 += __shfl_xor_sync(0xffffffffu, ss0, 1);
        ss0 += __shfl_xor_sync(0xffffffffu, ss0, 2);
        s8  += __shfl_xor_sync(0xffffffffu, s8, 1);
        s8  += __shfl_xor_sync(0xffffffffu, s8, 2);
        ss8 += __shfl_xor_sync(0xffffffffu, ss8, 1);
        ss8 += __shfl_xor_sync(0xffffffffu, ss8, 2);

        float m0 = s0 * (1.0f / H);
        float r0 = rsqrtf(ss0 * (1.0f / H) - m0 * m0 + 1e-5f);
        float m8 = s8 * (1.0f / H);
        float r8 = rsqrtf(ss8 * (1.0f / H) - m8 * m8 + 1e-5f);

        int eg  = i0 + g;
        int eg8 = i0 + g + 8;
        bool w0ok = eg < E, w8ok = eg8 < E;
        float* o0 = out + (size_t)eg  * H + 2 * c;
        float* o8 = out + (size_t)eg8 * H + 2 * c;
#pragma unroll
        for (int nf = 0; nf < 16; nf++) {
            float2 gg = *(const float2*)(slg + nf * 8 + 2 * c);
            float2 be = *(const float2*)(slb + nf * 8 + 2 * c);
            if (w0ok) {
                float y0 = (acc2[nf][0] - m0) * r0 * gg.x + be.x;
                float y1 = (acc2[nf][1] - m0) * r0 * gg.y + be.y;
                *(float2*)(o0 + nf * 8) = make_float2(y0, y1);
            }
            if (w8ok) {
                float y2 = (acc2[nf][2] - m8) * r8 * gg.x + be.x;
                float y3 = (acc2[nf][3] - m8) * r8 * gg.y + be.y;
                *(float2*)(o8 + nf * 8) = make_float2(y2, y3);
            }
        }
    }
}

// ================= launch =================
extern "C" void kernel_launch(void* const* d_in, const int* in_sizes, int n_in,
                              void* d_out, int out_size) {
    const float* x     = (const float*)d_in[0];
    const float* e     = (const float*)d_in[1];
    const float* u     = (const float*)d_in[2];
    const float* W1    = (const float*)d_in[3];
    const float* b1    = (const float*)d_in[4];
    const float* W2    = (const float*)d_in[5];
    const float* b2    = (const float*)d_in[6];
    const float* ln_g  = (const float*)d_in[7];
    const float* ln_b  = (const float*)d_in[8];
    const int*   eidx  = (const int*)d_in[9];
    const int*   batch = (const int*)d_in[10];
    float*       out   = (float*)d_out;

    int N = in_sizes[0] / D;   // 100000
    int E = in_sizes[1] / D;   // 1000000

    // smem: B1 frags 32KB + B2 frags 64KB + b2/lg/lb 1.5KB + pq 8*16*132*4
    const int SMEM = (4 * 16 * 32 + 8 * 16 * 32) * 16 + 3 * 128 * 4
                   + 8 * 16 * PQ_STRIDE * 4;   // = 167424 B
    cudaFuncSetAttribute(k_edge_mma, cudaFuncAttributeMaxDynamicSharedMemorySize, SMEM);

    k_preR<<<GDIM, H>>>(u, W1, b1);
    k_prePQ<<<(N + 7) / 8, 128>>>(x, W1, batch, N);
    k_edge_mma<<<152, 256, SMEM>>>(e, W1, W2, b2, ln_g, ln_b, eidx, out, E);
}